// round 16
// baseline (speedup 1.0000x reference)
#include <cuda_runtime.h>
#include <cuda_fp16.h>
#include <cstdint>

#define B_   8
#define N_   1024
#define D_   768
#define H_   12
#define HD_  64
#define M_TOT (B_ * N_)

__device__ __half g_x  [M_TOT * D_];
__device__ __half g_w  [4][D_ * D_];
__device__ __half g_q  [M_TOT * D_];      // head-major, pre-scaled by scale*log2e
__device__ __half g_k  [M_TOT * D_];
__device__ __half g_v  [M_TOT * D_];
__device__ __half g_ao [M_TOT * D_];

__device__ __forceinline__ uint32_t s2u(const void* p) {
    return (uint32_t)__cvta_generic_to_shared(p);
}
__device__ __forceinline__ void cp16(uint32_t s, const void* g) {
    asm volatile("cp.async.cg.shared.global [%0], [%1], 16;" :: "r"(s), "l"(g));
}
__device__ __forceinline__ void cp_commit() {
    asm volatile("cp.async.commit_group;");
}
__device__ __forceinline__ void ldm_x4(uint32_t& r0, uint32_t& r1,
                                       uint32_t& r2, uint32_t& r3, uint32_t a) {
    asm volatile("ldmatrix.sync.aligned.m8n8.x4.shared.b16 {%0,%1,%2,%3}, [%4];"
                 : "=r"(r0), "=r"(r1), "=r"(r2), "=r"(r3) : "r"(a));
}
__device__ __forceinline__ void ldm_x4t(uint32_t& r0, uint32_t& r1,
                                        uint32_t& r2, uint32_t& r3, uint32_t a) {
    asm volatile("ldmatrix.sync.aligned.m8n8.x4.trans.shared.b16 {%0,%1,%2,%3}, [%4];"
                 : "=r"(r0), "=r"(r1), "=r"(r2), "=r"(r3) : "r"(a));
}
__device__ __forceinline__ void mma16816(float* c, const uint32_t* a,
                                         uint32_t b0, uint32_t b1) {
    asm volatile(
        "mma.sync.aligned.m16n8k16.row.col.f32.f16.f16.f32 "
        "{%0,%1,%2,%3}, {%4,%5,%6,%7}, {%8,%9}, {%0,%1,%2,%3};"
        : "+f"(c[0]), "+f"(c[1]), "+f"(c[2]), "+f"(c[3])
        : "r"(a[0]), "r"(a[1]), "r"(a[2]), "r"(a[3]), "r"(b0), "r"(b1));
}
__device__ __forceinline__ uint32_t packh2(float a, float b) {
    __half2 h = __floats2half2_rn(a, b);
    return *reinterpret_cast<uint32_t*>(&h);
}
// Hardware exp2 (MUFU.EX2) on the otherwise-idle MUFU pipe.
__device__ __forceinline__ float ex2a(float x) {
    float y;
    asm("ex2.approx.f32 %0, %1;" : "=f"(y) : "f"(x));
    return y;
}

// ---------------------------------------------------------------------------
// Single fused conversion launch: x then Wq|Wk|Wv|Wo into contiguous fp16.
// ---------------------------------------------------------------------------
__global__ __launch_bounds__(256) void convall_kernel(
    const float* __restrict__ x,
    const float* __restrict__ W0, const float* __restrict__ W1,
    const float* __restrict__ W2, const float* __restrict__ W3,
    __half* __restrict__ xout, __half* __restrict__ wout,
    int nx4, int nw4)
{
    int i = blockIdx.x * blockDim.x + threadIdx.x;
    const float* src;
    __half* dst;
    int j;
    if (i < nx4) { src = x; dst = xout; j = i; }
    else {
        int k = i - nx4;
        if (k >= 4 * nw4) return;
        int sel = k / nw4;
        j = k - sel * nw4;
        src = (sel == 0) ? W0 : (sel == 1) ? W1 : (sel == 2) ? W2 : W3;
        dst = wout + (size_t)sel * (D_ * D_);
    }
    float4 v = reinterpret_cast<const float4*>(src)[j];
    reinterpret_cast<uint32_t*>(dst)[2 * j]     = packh2(v.x, v.y);
    reinterpret_cast<uint32_t*>(dst)[2 * j + 1] = packh2(v.z, v.w);
}

// ---------------------------------------------------------------------------
// Fused QKV GEMM (unchanged from R15): CTA 128x128, k-chunk 64, 3-stage
// cp.async pipeline, 110.6KB dynamic smem.
// ---------------------------------------------------------------------------
#define QSTR 72
#define QOP64 (128 * QSTR * 2)          // 18432 bytes per 128-row operand
#define QSTG  (2 * QOP64)               // 36864 per stage
#define QSMEM (3 * QSTG)                // 110592 total

__global__ __launch_bounds__(256, 2) void qkv_gemm(
    const __half* __restrict__ A, const __half* __restrict__ Wall,
    const float* __restrict__ bq, const float* __restrict__ bk,
    const float* __restrict__ bv,
    __half* __restrict__ Oq, __half* __restrict__ Ok, __half* __restrict__ Ov)
{
    extern __shared__ __align__(16) unsigned char smraw[];
    const uint32_t sbase = s2u(smraw);

    const int t      = threadIdx.x;
    const int lane   = t & 31;
    const int wid    = t >> 5;
    const int warp_m = wid & 1;
    const int warp_n = wid >> 1;
    const int bx     = blockIdx.x;
    const int proj   = bx / 6;
    const int bn     = (bx % 6) * 128;
    const int bm     = blockIdx.y * 128;

    const __half* W = Wall + (size_t)proj * D_ * D_;
    const float* bias = (proj == 0) ? bq : (proj == 1) ? bk : bv;
    __half* Out = (proj == 0) ? Oq : (proj == 1) ? Ok : Ov;
    const float oscale = (proj == 0)
        ? (float)(0.03608439182435161 * 1.4426950408889634) : 1.0f;

    float acc[4][4][4];
    #pragma unroll
    for (int i = 0; i < 4; i++)
        #pragma unroll
        for (int j = 0; j < 4; j++)
            #pragma unroll
            for (int r = 0; r < 4; r++) acc[i][j][r] = 0.f;

    auto issue = [&](int c, int stg) {
        const int kk = c * 64;
        const uint32_t sA = sbase + (uint32_t)(stg * QSTG);
        const uint32_t sB = sA + QOP64;
        #pragma unroll
        for (int j = 0; j < 4; j++) {
            int u   = t + j * 256;
            int row = u >> 3;
            int c16 = u & 7;
            uint32_t off = (uint32_t)(row * (QSTR * 2) + c16 * 16);
            cp16(sA + off, A + (size_t)(bm + row) * D_ + kk + c16 * 8);
            cp16(sB + off, W + (size_t)(bn + row) * D_ + kk + c16 * 8);
        }
        cp_commit();
    };

    issue(0, 0); issue(1, 1); issue(2, 2);

    for (int cb = 0; cb < 4; cb++) {
        #pragma unroll
        for (int u = 0; u < 3; u++) {
            const int c = cb * 3 + u;
            asm volatile("cp.async.wait_group 2;");
            __syncthreads();

            const uint32_t sA = sbase + (uint32_t)(u * QSTG);
            const uint32_t sB = sA + QOP64;

            #pragma unroll
            for (int ko = 0; ko < 4; ko++) {
                const int k0 = ko * 16;
                uint32_t af[4][4];
                #pragma unroll
                for (int i = 0; i < 4; i++) {
                    int mrow = warp_m * 64 + i * 16 + (lane & 15);
                    uint32_t a = sA + (uint32_t)((mrow * QSTR + k0 + (lane >> 4) * 8) * 2);
                    ldm_x4(af[i][0], af[i][1], af[i][2], af[i][3], a);
                }
                uint32_t bfr[4][2];
                #pragma unroll
                for (int p = 0; p < 2; p++) {
                    int nrow = warp_n * 32 + p * 16 + (lane & 7) + ((lane >> 4) & 1) * 8;
                    uint32_t a = sB + (uint32_t)((nrow * QSTR + k0 + ((lane >> 3) & 1) * 8) * 2);
                    uint32_t r0, r1, r2, r3;
                    ldm_x4(r0, r1, r2, r3, a);
                    bfr[p * 2][0] = r0; bfr[p * 2][1] = r1;
                    bfr[p * 2 + 1][0] = r2; bfr[p * 2 + 1][1] = r3;
                }
                #pragma unroll
                for (int i = 0; i < 4; i++)
                    #pragma unroll
                    for (int j = 0; j < 4; j++)
                        mma16816(acc[i][j], af[i], bfr[j][0], bfr[j][1]);
            }
            __syncthreads();
            if (c + 3 < 12) issue(c + 3, u); else cp_commit();
        }
    }

    #pragma unroll
    for (int j = 0; j < 4; j++) {
        const int col = bn + warp_n * 32 + j * 8 + (lane & 3) * 2;
        const float2 bvv = *reinterpret_cast<const float2*>(bias + col);
        const int hidx = col >> 6, d = col & 63;
        #pragma unroll
        for (int i = 0; i < 4; i++) {
            const int row0 = bm + warp_m * 64 + i * 16 + (lane >> 2);
            const int b = row0 >> 10, n = row0 & 1023;
            size_t dst = ((size_t)(b * H_ + hidx) * N_ + n) * HD_ + d;
            *reinterpret_cast<uint32_t*>(Out + dst) =
                packh2((acc[i][j][0] + bvv.x) * oscale, (acc[i][j][1] + bvv.y) * oscale);
            *reinterpret_cast<uint32_t*>(Out + dst + 8 * HD_) =
                packh2((acc[i][j][2] + bvv.x) * oscale, (acc[i][j][3] + bvv.y) * oscale);
        }
    }
}

// ---------------------------------------------------------------------------
// Output projection: CTA 128x64, 8 warps (4x2), k-chunk 128 (6 iterations),
// double-buffered dynamic smem (102KB). Same k0 sequence -> bit-identical.
// ---------------------------------------------------------------------------
#define OSTR 136                        // 128 + 8 halves pad (272B rows)
#define OA128 (128 * OSTR * 2)          // 34816
#define OB128 (64 * OSTR * 2)           // 17408
#define OSTG128 (OA128 + OB128)         // 52224 per stage
#define OSMEM (2 * OSTG128)             // 104448 total

__global__ __launch_bounds__(256, 2) void out_gemm(
    const __half* __restrict__ A, const __half* __restrict__ W,
    const float* __restrict__ bias, float* __restrict__ C)
{
    extern __shared__ __align__(16) unsigned char smraw[];
    const uint32_t sbase = s2u(smraw);

    const int t      = threadIdx.x;
    const int lane   = t & 31;
    const int wid    = t >> 5;
    const int warp_m = wid & 3;
    const int warp_n = wid >> 2;
    const int bn     = blockIdx.x * 64;
    const int bm     = blockIdx.y * 128;

    float acc[2][4][4];
    #pragma unroll
    for (int i = 0; i < 2; i++)
        #pragma unroll
        for (int j = 0; j < 4; j++)
            #pragma unroll
            for (int r = 0; r < 4; r++) acc[i][j][r] = 0.f;

    auto issue = [&](int c, int stg) {
        const int kk = c * 128;
        const uint32_t sA = sbase + (uint32_t)(stg * OSTG128);
        const uint32_t sB = sA + OA128;
        // A: 128 rows x 256B = 16 x 16B chunks per row (2048 cp16 / 256 thr = 8)
        #pragma unroll
        for (int j = 0; j < 8; j++) {
            int u   = t + j * 256;
            int row = u >> 4;
            int c16 = u & 15;
            cp16(sA + (uint32_t)(row * (OSTR * 2) + c16 * 16),
                 A + (size_t)(bm + row) * D_ + kk + c16 * 8);
        }
        // B: 64 rows x 16 chunks = 1024 cp16 / 256 thr = 4
        #pragma unroll
        for (int j = 0; j < 4; j++) {
            int u   = t + j * 256;
            int row = u >> 4;
            int c16 = u & 15;
            cp16(sB + (uint32_t)(row * (OSTR * 2) + c16 * 16),
                 W + (size_t)(bn + row) * D_ + kk + c16 * 8);
        }
        cp_commit();
    };

    issue(0, 0);
    issue(1, 1);

    for (int c = 0; c < 6; c++) {
        const int buf = c & 1;
        if (c < 5) { asm volatile("cp.async.wait_group 1;"); }
        else       { asm volatile("cp.async.wait_group 0;"); }
        __syncthreads();

        const uint32_t sA = sbase + (uint32_t)(buf * OSTG128);
        const uint32_t sB = sA + OA128;

        #pragma unroll
        for (int ko = 0; ko < 8; ko++) {
            const int k0 = ko * 16;
            uint32_t af[2][4];
            #pragma unroll
            for (int i = 0; i < 2; i++) {
                int mrow = warp_m * 32 + i * 16 + (lane & 15);
                uint32_t a = sA + (uint32_t)((mrow * OSTR + k0 + (lane >> 4) * 8) * 2);
                ldm_x4(af[i][0], af[i][1], af[i][2], af[i][3], a);
            }
            uint32_t bfr[4][2];
            #pragma unroll
            for (int p = 0; p < 2; p++) {
                int nrow = warp_n * 32 + p * 16 + (lane & 7) + ((lane >> 4) & 1) * 8;
                uint32_t a = sB + (uint32_t)((nrow * OSTR + k0 + ((lane >> 3) & 1) * 8) * 2);
                uint32_t r0, r1, r2, r3;
                ldm_x4(r0, r1, r2, r3, a);
                bfr[p * 2][0] = r0; bfr[p * 2][1] = r1;
                bfr[p * 2 + 1][0] = r2; bfr[p * 2 + 1][1] = r3;
            }
            #pragma unroll
            for (int i = 0; i < 2; i++)
                #pragma unroll
                for (int j = 0; j < 4; j++)
                    mma16816(acc[i][j], af[i], bfr[j][0], bfr[j][1]);
        }
        __syncthreads();
        if (c + 2 < 6) issue(c + 2, buf); else cp_commit();
    }

    #pragma unroll
    for (int j = 0; j < 4; j++) {
        const int col = bn + warp_n * 32 + j * 8 + (lane & 3) * 2;
        const float2 bv = *reinterpret_cast<const float2*>(bias + col);
        #pragma unroll
        for (int i = 0; i < 2; i++) {
            const int row0 = bm + warp_m * 32 + i * 16 + (lane >> 2);
            float2 a0; a0.x = acc[i][j][0] + bv.x; a0.y = acc[i][j][1] + bv.y;
            float2 a1; a1.x = acc[i][j][2] + bv.x; a1.y = acc[i][j][3] + bv.y;
            *reinterpret_cast<float2*>(C + (size_t)row0 * D_ + col) = a0;
            *reinterpret_cast<float2*>(C + (size_t)(row0 + 8) * D_ + col) = a1;
        }
    }
}

// ---------------------------------------------------------------------------
// Flash attention (unchanged from R14/R15): 4 warps x 32 q-rows, 4-stage
// pipeline, 1 barrier/tile, MUFU exp2.
// ---------------------------------------------------------------------------
#define AT_STRIDE 72
#define ARR_H (32 * AT_STRIDE)
#define STG_H (2 * ARR_H)
#define STG_BYTES (STG_H * 2)

__global__ __launch_bounds__(128, 3) void attn_mma(
    const __half* __restrict__ Q, const __half* __restrict__ K,
    const __half* __restrict__ V, __half* __restrict__ ao)
{
    __shared__ __align__(16) __half sm[4 * STG_H];   // 36864
    const uint32_t smb = s2u(sm);

    const int t     = threadIdx.x;
    const int lane  = t & 31;
    const int warp  = t >> 5;
    const int bh    = blockIdx.y;
    const int qbase = blockIdx.x * 128;
    const size_t head = (size_t)bh * N_ * HD_;

    #pragma unroll
    for (int j = 0; j < 8; j++) {
        int u = t + j * 128;
        int r = u >> 3, ch = u & 7;
        cp16(smb + (uint32_t)((r * AT_STRIDE + ch * 8) * 2),
             Q + head + (size_t)(qbase + r) * HD_ + ch * 8);
    }
    cp_commit();
    asm volatile("cp.async.wait_group 0;");
    __syncthreads();

    uint32_t qf[2][4][4];
    #pragma unroll
    for (int mt = 0; mt < 2; mt++)
        #pragma unroll
        for (int ks = 0; ks < 4; ks++) {
            uint32_t a = smb + (uint32_t)(((warp * 32 + mt * 16 + (lane & 15)) * AT_STRIDE
                                           + ks * 16 + (lane >> 4) * 8) * 2);
            ldm_x4(qf[mt][ks][0], qf[mt][ks][1], qf[mt][ks][2], qf[mt][ks][3], a);
        }
    __syncthreads();

    const uint32_t qk0 = smb
        + (uint32_t)((((lane & 7) + ((lane >> 4) & 1) * 8) * AT_STRIDE) * 2)
        + (uint32_t)(((lane >> 3) & 1) * 16);
    const uint32_t qk1 = qk0 + 16 * AT_STRIDE * 2;
    const uint32_t pv0 = smb + ARR_H * 2
        + (uint32_t)(((lane & 15) * AT_STRIDE + (lane >> 4) * 8) * 2);
    const uint32_t pv1 = pv0 + 16 * AT_STRIDE * 2;

    auto issue_kv = [&](int kt) {
        const uint32_t so = (uint32_t)((kt & 3) * STG_BYTES);
        #pragma unroll
        for (int j = 0; j < 2; j++) {
            int u = t + j * 128;
            int r = u >> 3, ch = u & 7;
            uint32_t off = so + (uint32_t)((r * AT_STRIDE + ch * 8) * 2);
            size_t g = head + (size_t)(kt * 32 + r) * HD_ + ch * 8;
            cp16(smb + off,             K + g);
            cp16(smb + ARR_H * 2 + off, V + g);
        }
        cp_commit();
    };

    float Oa[2][8][4];
    #pragma unroll
    for (int mt = 0; mt < 2; mt++)
        #pragma unroll
        for (int i = 0; i < 8; i++)
            #pragma unroll
            for (int r = 0; r < 4; r++) Oa[mt][i][r] = 0.f;
    float lsum[2][2] = {{0.f, 0.f}, {0.f, 0.f}};

    auto compute = [&](int u) {
        const uint32_t so = (uint32_t)(u * STG_BYTES);
        uint32_t pf[2][2][4];

        #pragma unroll
        for (int ng = 0; ng < 2; ng++) {
            float S[2][2][4];
            #pragma unroll
            for (int mt = 0; mt < 2; mt++)
                #pragma unroll
                for (int nt = 0; nt < 2; nt++)
                    #pragma unroll
                    for (int r = 0; r < 4; r++) S[mt][nt][r] = 0.f;

            const uint32_t base = (ng ? qk1 : qk0) + so;
            #pragma unroll
            for (int ks = 0; ks < 4; ks++) {
                uint32_t h0, h1, h2, h3;
                ldm_x4(h0, h1, h2, h3, base + ks * 32);
                mma16816(S[0][0], qf[0][ks], h0, h1);
                mma16816(S[0][1], qf[0][ks], h2, h3);
                mma16816(S[1][0], qf[1][ks], h0, h1);
                mma16816(S[1][1], qf[1][ks], h2, h3);
            }

            #pragma unroll
            for (int mt = 0; mt < 2; mt++) {
                #pragma unroll
                for (int nt = 0; nt < 2; nt++) {
                    #pragma unroll
                    for (int r = 0; r < 4; r++) S[mt][nt][r] = ex2a(S[mt][nt][r]);
                    lsum[mt][0] += S[mt][nt][0] + S[mt][nt][1];
                    lsum[mt][1] += S[mt][nt][2] + S[mt][nt][3];
                }
                pf[mt][ng][0] = packh2(S[mt][0][0], S[mt][0][1]);
                pf[mt][ng][1] = packh2(S[mt][0][2], S[mt][0][3]);
                pf[mt][ng][2] = packh2(S[mt][1][0], S[mt][1][1]);
                pf[mt][ng][3] = packh2(S[mt][1][2], S[mt][1][3]);
            }
        }

        #pragma unroll
        for (int ks = 0; ks < 2; ks++) {
            const uint32_t base = (ks ? pv1 : pv0) + so;
            #pragma unroll
            for (int dg = 0; dg < 4; dg++) {
                uint32_t v0, v1, v2, v3;
                ldm_x4t(v0, v1, v2, v3, base + dg * 32);
                mma16816(Oa[0][2 * dg],     pf[0][ks], v0, v1);
                mma16816(Oa[0][2 * dg + 1], pf[0][ks], v2, v3);
                mma16816(Oa[1][2 * dg],     pf[1][ks], v0, v1);
                mma16816(Oa[1][2 * dg + 1], pf[1][ks], v2, v3);
            }
        }
    };

    issue_kv(0); issue_kv(1); issue_kv(2);

    for (int kt4 = 0; kt4 < 7; kt4++) {
        #pragma unroll
        for (int u = 0; u < 4; u++) {
            asm volatile("cp.async.wait_group 2;");
            __syncthreads();
            issue_kv(kt4 * 4 + u + 3);
            compute(u);
        }
    }
    asm volatile("cp.async.wait_group 2;"); __syncthreads(); issue_kv(31); compute(0);
    asm volatile("cp.async.wait_group 2;"); __syncthreads(); compute(1);
    asm volatile("cp.async.wait_group 1;"); __syncthreads(); compute(2);
    asm volatile("cp.async.wait_group 0;"); __syncthreads(); compute(3);

    #pragma unroll
    for (int mt = 0; mt < 2; mt++)
        #pragma unroll
        for (int s = 0; s < 2; s++) {
            lsum[mt][s] += __shfl_xor_sync(0xffffffffu, lsum[mt][s], 1);
            lsum[mt][s] += __shfl_xor_sync(0xffffffffu, lsum[mt][s], 2);
        }

    const int b = bh / H_, h = bh % H_;
    #pragma unroll
    for (int mt = 0; mt < 2; mt++) {
        const float inv0 = 1.f / lsum[mt][0];
        const float inv1 = 1.f / lsum[mt][1];
        const size_t row0 = (size_t)b * N_ + qbase + warp * 32 + mt * 16 + (lane >> 2);
        #pragma unroll
        for (int dt = 0; dt < 8; dt++) {
            const int col = h * HD_ + dt * 8 + (lane & 3) * 2;
            *reinterpret_cast<uint32_t*>(ao + row0 * D_ + col) =
                packh2(Oa[mt][dt][0] * inv0, Oa[mt][dt][1] * inv0);
            *reinterpret_cast<uint32_t*>(ao + (row0 + 8) * D_ + col) =
                packh2(Oa[mt][dt][2] * inv1, Oa[mt][dt][3] * inv1);
        }
    }
}

// ---------------------------------------------------------------------------
extern "C" void kernel_launch(void* const* d_in, const int* in_sizes, int n_in,
                              void* d_out, int out_size)
{
    const float* x  = (const float*)d_in[0];
    const float* Wq = (const float*)d_in[1];
    const float* bq = (const float*)d_in[2];
    const float* Wk = (const float*)d_in[3];
    const float* bk = (const float*)d_in[4];
    const float* Wv = (const float*)d_in[5];
    const float* bv = (const float*)d_in[6];
    const float* Wo = (const float*)d_in[7];
    const float* bo = (const float*)d_in[8];
    float* out = (float*)d_out;

    __half *xh, *w, *q, *k, *v, *ao;
    cudaGetSymbolAddress((void**)&xh, g_x);
    cudaGetSymbolAddress((void**)&w,  g_w);
    cudaGetSymbolAddress((void**)&q,  g_q);
    cudaGetSymbolAddress((void**)&k,  g_k);
    cudaGetSymbolAddress((void**)&v,  g_v);
    cudaGetSymbolAddress((void**)&ao, g_ao);

    const int nx4 = M_TOT * D_ / 4;
    const int nw4 = D_ * D_ / 4;
    const size_t WS = (size_t)D_ * D_;
    const int ntot = nx4 + 4 * nw4;

    static bool attr_done = false;
    if (!attr_done) {
        cudaFuncSetAttribute(qkv_gemm, cudaFuncAttributeMaxDynamicSharedMemorySize, QSMEM);
        cudaFuncSetAttribute(out_gemm, cudaFuncAttributeMaxDynamicSharedMemorySize, OSMEM);
        attr_done = true;
    }

    convall_kernel<<<(ntot + 255) / 256, 256>>>(x, Wq, Wk, Wv, Wo, xh, w, nx4, nw4);

    dim3 qkvgrid(18, M_TOT / 128);
    qkv_gemm<<<qkvgrid, 256, QSMEM>>>(xh, w, bq, bk, bv, q, k, v);

    dim3 agrid(N_ / 128, B_ * H_);
    attn_mma<<<agrid, 128>>>(q, k, v, ao);

    dim3 ogrid(12, M_TOT / 128);
    out_gemm<<<ogrid, 256, OSMEM>>>(ao, w + 3 * WS, bo, out);
}

// round 17
// speedup vs baseline: 1.0175x; 1.0175x over previous
#include <cuda_runtime.h>
#include <cuda_fp16.h>
#include <cstdint>

#define B_   8
#define N_   1024
#define D_   768
#define H_   12
#define HD_  64
#define M_TOT (B_ * N_)

__device__ __half g_x  [M_TOT * D_];
__device__ __half g_w  [4][D_ * D_];
__device__ __half g_q  [M_TOT * D_];      // head-major, pre-scaled by scale*log2e
__device__ __half g_k  [M_TOT * D_];
__device__ __half g_v  [M_TOT * D_];
__device__ __half g_ao [M_TOT * D_];

__device__ __forceinline__ uint32_t s2u(const void* p) {
    return (uint32_t)__cvta_generic_to_shared(p);
}
__device__ __forceinline__ void cp16(uint32_t s, const void* g) {
    asm volatile("cp.async.cg.shared.global [%0], [%1], 16;" :: "r"(s), "l"(g));
}
__device__ __forceinline__ void cp_commit() {
    asm volatile("cp.async.commit_group;");
}
__device__ __forceinline__ void ldm_x4(uint32_t& r0, uint32_t& r1,
                                       uint32_t& r2, uint32_t& r3, uint32_t a) {
    asm volatile("ldmatrix.sync.aligned.m8n8.x4.shared.b16 {%0,%1,%2,%3}, [%4];"
                 : "=r"(r0), "=r"(r1), "=r"(r2), "=r"(r3) : "r"(a));
}
__device__ __forceinline__ void ldm_x4t(uint32_t& r0, uint32_t& r1,
                                        uint32_t& r2, uint32_t& r3, uint32_t a) {
    asm volatile("ldmatrix.sync.aligned.m8n8.x4.trans.shared.b16 {%0,%1,%2,%3}, [%4];"
                 : "=r"(r0), "=r"(r1), "=r"(r2), "=r"(r3) : "r"(a));
}
__device__ __forceinline__ void mma16816(float* c, const uint32_t* a,
                                         uint32_t b0, uint32_t b1) {
    asm volatile(
        "mma.sync.aligned.m16n8k16.row.col.f32.f16.f16.f32 "
        "{%0,%1,%2,%3}, {%4,%5,%6,%7}, {%8,%9}, {%0,%1,%2,%3};"
        : "+f"(c[0]), "+f"(c[1]), "+f"(c[2]), "+f"(c[3])
        : "r"(a[0]), "r"(a[1]), "r"(a[2]), "r"(a[3]), "r"(b0), "r"(b1));
}
__device__ __forceinline__ uint32_t packh2(float a, float b) {
    __half2 h = __floats2half2_rn(a, b);
    return *reinterpret_cast<uint32_t*>(&h);
}
// Hardware exp2 (MUFU.EX2) on the otherwise-idle MUFU pipe.
__device__ __forceinline__ float ex2a(float x) {
    float y;
    asm("ex2.approx.f32 %0, %1;" : "=f"(y) : "f"(x));
    return y;
}

// ---------------------------------------------------------------------------
// Fused conversion: 4 independent float4 per thread (MLP=4 front-batched
// loads -> hides DRAM latency; previous version was MLP=1, issue=6%).
// Same elements, same math, same destinations -> bit-identical outputs.
// ---------------------------------------------------------------------------
__global__ __launch_bounds__(256) void convall_kernel(
    const float* __restrict__ x,
    const float* __restrict__ W0, const float* __restrict__ W1,
    const float* __restrict__ W2, const float* __restrict__ W3,
    __half* __restrict__ xout, __half* __restrict__ wout,
    int nx4, int nw4)
{
    const int base = blockIdx.x * 1024 + threadIdx.x;
    const int ntot = nx4 + 4 * nw4;

    const float* srcs[4];
    uint32_t* dsts[4];
    float4 vals[4];
    int js[4];
    bool act[4];

    #pragma unroll
    for (int s = 0; s < 4; s++) {
        int i = base + s * 256;
        act[s] = (i < ntot);
        const float* src = x;
        __half* dst = xout;
        int j = i;
        if (i >= nx4) {
            int k = i - nx4;
            int sel = k / nw4;
            j = k - sel * nw4;
            src = (sel == 0) ? W0 : (sel == 1) ? W1 : (sel == 2) ? W2 : W3;
            dst = wout + (size_t)sel * (D_ * D_);
        }
        srcs[s] = src;
        dsts[s] = reinterpret_cast<uint32_t*>(dst);
        js[s] = j;
        if (act[s]) vals[s] = reinterpret_cast<const float4*>(src)[j];
    }
    #pragma unroll
    for (int s = 0; s < 4; s++) {
        if (!act[s]) continue;
        dsts[s][2 * js[s]]     = packh2(vals[s].x, vals[s].y);
        dsts[s][2 * js[s] + 1] = packh2(vals[s].z, vals[s].w);
    }
}

// ---------------------------------------------------------------------------
// Fused QKV GEMM (R15 form, known-good): CTA 128x128, k-chunk 64, 3-stage
// cp.async pipeline, 110.6KB dynamic smem.
// ---------------------------------------------------------------------------
#define QSTR 72
#define QOP64 (128 * QSTR * 2)          // 18432 bytes per 128-row operand
#define QSTG  (2 * QOP64)               // 36864 per stage
#define QSMEM (3 * QSTG)                // 110592 total

__global__ __launch_bounds__(256, 2) void qkv_gemm(
    const __half* __restrict__ A, const __half* __restrict__ Wall,
    const float* __restrict__ bq, const float* __restrict__ bk,
    const float* __restrict__ bv,
    __half* __restrict__ Oq, __half* __restrict__ Ok, __half* __restrict__ Ov)
{
    extern __shared__ __align__(16) unsigned char smraw[];
    const uint32_t sbase = s2u(smraw);

    const int t      = threadIdx.x;
    const int lane   = t & 31;
    const int wid    = t >> 5;
    const int warp_m = wid & 1;
    const int warp_n = wid >> 1;
    const int bx     = blockIdx.x;
    const int proj   = bx / 6;
    const int bn     = (bx % 6) * 128;
    const int bm     = blockIdx.y * 128;

    const __half* W = Wall + (size_t)proj * D_ * D_;
    const float* bias = (proj == 0) ? bq : (proj == 1) ? bk : bv;
    __half* Out = (proj == 0) ? Oq : (proj == 1) ? Ok : Ov;
    const float oscale = (proj == 0)
        ? (float)(0.03608439182435161 * 1.4426950408889634) : 1.0f;

    float acc[4][4][4];
    #pragma unroll
    for (int i = 0; i < 4; i++)
        #pragma unroll
        for (int j = 0; j < 4; j++)
            #pragma unroll
            for (int r = 0; r < 4; r++) acc[i][j][r] = 0.f;

    auto issue = [&](int c, int stg) {
        const int kk = c * 64;
        const uint32_t sA = sbase + (uint32_t)(stg * QSTG);
        const uint32_t sB = sA + QOP64;
        #pragma unroll
        for (int j = 0; j < 4; j++) {
            int u   = t + j * 256;
            int row = u >> 3;
            int c16 = u & 7;
            uint32_t off = (uint32_t)(row * (QSTR * 2) + c16 * 16);
            cp16(sA + off, A + (size_t)(bm + row) * D_ + kk + c16 * 8);
            cp16(sB + off, W + (size_t)(bn + row) * D_ + kk + c16 * 8);
        }
        cp_commit();
    };

    issue(0, 0); issue(1, 1); issue(2, 2);

    for (int cb = 0; cb < 4; cb++) {
        #pragma unroll
        for (int u = 0; u < 3; u++) {
            const int c = cb * 3 + u;
            asm volatile("cp.async.wait_group 2;");
            __syncthreads();

            const uint32_t sA = sbase + (uint32_t)(u * QSTG);
            const uint32_t sB = sA + QOP64;

            #pragma unroll
            for (int ko = 0; ko < 4; ko++) {
                const int k0 = ko * 16;
                uint32_t af[4][4];
                #pragma unroll
                for (int i = 0; i < 4; i++) {
                    int mrow = warp_m * 64 + i * 16 + (lane & 15);
                    uint32_t a = sA + (uint32_t)((mrow * QSTR + k0 + (lane >> 4) * 8) * 2);
                    ldm_x4(af[i][0], af[i][1], af[i][2], af[i][3], a);
                }
                uint32_t bfr[4][2];
                #pragma unroll
                for (int p = 0; p < 2; p++) {
                    int nrow = warp_n * 32 + p * 16 + (lane & 7) + ((lane >> 4) & 1) * 8;
                    uint32_t a = sB + (uint32_t)((nrow * QSTR + k0 + ((lane >> 3) & 1) * 8) * 2);
                    uint32_t r0, r1, r2, r3;
                    ldm_x4(r0, r1, r2, r3, a);
                    bfr[p * 2][0] = r0; bfr[p * 2][1] = r1;
                    bfr[p * 2 + 1][0] = r2; bfr[p * 2 + 1][1] = r3;
                }
                #pragma unroll
                for (int i = 0; i < 4; i++)
                    #pragma unroll
                    for (int j = 0; j < 4; j++)
                        mma16816(acc[i][j], af[i], bfr[j][0], bfr[j][1]);
            }
            __syncthreads();
            if (c + 3 < 12) issue(c + 3, u); else cp_commit();
        }
    }

    #pragma unroll
    for (int j = 0; j < 4; j++) {
        const int col = bn + warp_n * 32 + j * 8 + (lane & 3) * 2;
        const float2 bvv = *reinterpret_cast<const float2*>(bias + col);
        const int hidx = col >> 6, d = col & 63;
        #pragma unroll
        for (int i = 0; i < 4; i++) {
            const int row0 = bm + warp_m * 64 + i * 16 + (lane >> 2);
            const int b = row0 >> 10, n = row0 & 1023;
            size_t dst = ((size_t)(b * H_ + hidx) * N_ + n) * HD_ + d;
            *reinterpret_cast<uint32_t*>(Out + dst) =
                packh2((acc[i][j][0] + bvv.x) * oscale, (acc[i][j][1] + bvv.y) * oscale);
            *reinterpret_cast<uint32_t*>(Out + dst + 8 * HD_) =
                packh2((acc[i][j][2] + bvv.x) * oscale, (acc[i][j][3] + bvv.y) * oscale);
        }
    }
}

// ---------------------------------------------------------------------------
// Output projection (R15 form, known-good): CTA 128x64, 8 warps (4x2),
// k-chunk 64 (12 iterations), THREE-stage cp.async pipeline (83KB smem).
// ---------------------------------------------------------------------------
#define OA64 (128 * QSTR * 2)           // 18432
#define OB64 (64 * QSTR * 2)            // 9216
#define OSTG64 (OA64 + OB64)            // 27648 per stage
#define OSMEM (3 * OSTG64)              // 82944 total

__global__ __launch_bounds__(256, 2) void out_gemm(
    const __half* __restrict__ A, const __half* __restrict__ W,
    const float* __restrict__ bias, float* __restrict__ C)
{
    extern __shared__ __align__(16) unsigned char smraw[];
    const uint32_t sbase = s2u(smraw);

    const int t      = threadIdx.x;
    const int lane   = t & 31;
    const int wid    = t >> 5;
    const int warp_m = wid & 3;
    const int warp_n = wid >> 2;
    const int bn     = blockIdx.x * 64;
    const int bm     = blockIdx.y * 128;

    float acc[2][4][4];
    #pragma unroll
    for (int i = 0; i < 2; i++)
        #pragma unroll
        for (int j = 0; j < 4; j++)
            #pragma unroll
            for (int r = 0; r < 4; r++) acc[i][j][r] = 0.f;

    auto issue = [&](int c, int stg) {
        const int kk = c * 64;
        const uint32_t sA = sbase + (uint32_t)(stg * OSTG64);
        const uint32_t sB = sA + OA64;
        #pragma unroll
        for (int j = 0; j < 4; j++) {
            int u   = t + j * 256;
            int row = u >> 3;
            int c16 = u & 7;
            cp16(sA + (uint32_t)(row * (QSTR * 2) + c16 * 16),
                 A + (size_t)(bm + row) * D_ + kk + c16 * 8);
        }
        #pragma unroll
        for (int j = 0; j < 2; j++) {
            int u   = t + j * 256;
            int row = u >> 3;
            int c16 = u & 7;
            cp16(sB + (uint32_t)(row * (QSTR * 2) + c16 * 16),
                 W + (size_t)(bn + row) * D_ + kk + c16 * 8);
        }
        cp_commit();
    };

    issue(0, 0); issue(1, 1); issue(2, 2);

    for (int cb = 0; cb < 4; cb++) {
        #pragma unroll
        for (int u = 0; u < 3; u++) {
            const int c = cb * 3 + u;
            asm volatile("cp.async.wait_group 2;");
            __syncthreads();

            const uint32_t sA = sbase + (uint32_t)(u * OSTG64);
            const uint32_t sB = sA + OA64;

            #pragma unroll
            for (int ko = 0; ko < 4; ko++) {
                const int k0 = ko * 16;
                uint32_t af[2][4];
                #pragma unroll
                for (int i = 0; i < 2; i++) {
                    int mrow = warp_m * 32 + i * 16 + (lane & 15);
                    uint32_t a = sA + (uint32_t)((mrow * QSTR + k0 + (lane >> 4) * 8) * 2);
                    ldm_x4(af[i][0], af[i][1], af[i][2], af[i][3], a);
                }
                uint32_t bfr[4][2];
                #pragma unroll
                for (int p = 0; p < 2; p++) {
                    int nrow = warp_n * 32 + p * 16 + (lane & 7) + ((lane >> 4) & 1) * 8;
                    uint32_t a = sB + (uint32_t)((nrow * QSTR + k0 + ((lane >> 3) & 1) * 8) * 2);
                    uint32_t r0, r1, r2, r3;
                    ldm_x4(r0, r1, r2, r3, a);
                    bfr[p * 2][0] = r0; bfr[p * 2][1] = r1;
                    bfr[p * 2 + 1][0] = r2; bfr[p * 2 + 1][1] = r3;
                }
                #pragma unroll
                for (int i = 0; i < 2; i++)
                    #pragma unroll
                    for (int j = 0; j < 4; j++)
                        mma16816(acc[i][j], af[i], bfr[j][0], bfr[j][1]);
            }
            __syncthreads();
            if (c + 3 < 12) issue(c + 3, u); else cp_commit();
        }
    }

    #pragma unroll
    for (int j = 0; j < 4; j++) {
        const int col = bn + warp_n * 32 + j * 8 + (lane & 3) * 2;
        const float2 bv = *reinterpret_cast<const float2*>(bias + col);
        #pragma unroll
        for (int i = 0; i < 2; i++) {
            const int row0 = bm + warp_m * 32 + i * 16 + (lane >> 2);
            float2 a0; a0.x = acc[i][j][0] + bv.x; a0.y = acc[i][j][1] + bv.y;
            float2 a1; a1.x = acc[i][j][2] + bv.x; a1.y = acc[i][j][3] + bv.y;
            *reinterpret_cast<float2*>(C + (size_t)row0 * D_ + col) = a0;
            *reinterpret_cast<float2*>(C + (size_t)(row0 + 8) * D_ + col) = a1;
        }
    }
}

// ---------------------------------------------------------------------------
// Flash attention (unchanged, known-good): 4 warps x 32 q-rows, 4-stage
// pipeline, 1 barrier/tile, MUFU exp2.
// ---------------------------------------------------------------------------
#define AT_STRIDE 72
#define ARR_H (32 * AT_STRIDE)
#define STG_H (2 * ARR_H)
#define STG_BYTES (STG_H * 2)

__global__ __launch_bounds__(128, 3) void attn_mma(
    const __half* __restrict__ Q, const __half* __restrict__ K,
    const __half* __restrict__ V, __half* __restrict__ ao)
{
    __shared__ __align__(16) __half sm[4 * STG_H];   // 36864
    const uint32_t smb = s2u(sm);

    const int t     = threadIdx.x;
    const int lane  = t & 31;
    const int warp  = t >> 5;
    const int bh    = blockIdx.y;
    const int qbase = blockIdx.x * 128;
    const size_t head = (size_t)bh * N_ * HD_;

    #pragma unroll
    for (int j = 0; j < 8; j++) {
        int u = t + j * 128;
        int r = u >> 3, ch = u & 7;
        cp16(smb + (uint32_t)((r * AT_STRIDE + ch * 8) * 2),
             Q + head + (size_t)(qbase + r) * HD_ + ch * 8);
    }
    cp_commit();
    asm volatile("cp.async.wait_group 0;");
    __syncthreads();

    uint32_t qf[2][4][4];
    #pragma unroll
    for (int mt = 0; mt < 2; mt++)
        #pragma unroll
        for (int ks = 0; ks < 4; ks++) {
            uint32_t a = smb + (uint32_t)(((warp * 32 + mt * 16 + (lane & 15)) * AT_STRIDE
                                           + ks * 16 + (lane >> 4) * 8) * 2);
            ldm_x4(qf[mt][ks][0], qf[mt][ks][1], qf[mt][ks][2], qf[mt][ks][3], a);
        }
    __syncthreads();

    const uint32_t qk0 = smb
        + (uint32_t)((((lane & 7) + ((lane >> 4) & 1) * 8) * AT_STRIDE) * 2)
        + (uint32_t)(((lane >> 3) & 1) * 16);
    const uint32_t qk1 = qk0 + 16 * AT_STRIDE * 2;
    const uint32_t pv0 = smb + ARR_H * 2
        + (uint32_t)(((lane & 15) * AT_STRIDE + (lane >> 4) * 8) * 2);
    const uint32_t pv1 = pv0 + 16 * AT_STRIDE * 2;

    auto issue_kv = [&](int kt) {
        const uint32_t so = (uint32_t)((kt & 3) * STG_BYTES);
        #pragma unroll
        for (int j = 0; j < 2; j++) {
            int u = t + j * 128;
            int r = u >> 3, ch = u & 7;
            uint32_t off = so + (uint32_t)((r * AT_STRIDE + ch * 8) * 2);
            size_t g = head + (size_t)(kt * 32 + r) * HD_ + ch * 8;
            cp16(smb + off,             K + g);
            cp16(smb + ARR_H * 2 + off, V + g);
        }
        cp_commit();
    };

    float Oa[2][8][4];
    #pragma unroll
    for (int mt = 0; mt < 2; mt++)
        #pragma unroll
        for (int i = 0; i < 8; i++)
            #pragma unroll
            for (int r = 0; r < 4; r++) Oa[mt][i][r] = 0.f;
    float lsum[2][2] = {{0.f, 0.f}, {0.f, 0.f}};

    auto compute = [&](int u) {
        const uint32_t so = (uint32_t)(u * STG_BYTES);
        uint32_t pf[2][2][4];

        #pragma unroll
        for (int ng = 0; ng < 2; ng++) {
            float S[2][2][4];
            #pragma unroll
            for (int mt = 0; mt < 2; mt++)
                #pragma unroll
                for (int nt = 0; nt < 2; nt++)
                    #pragma unroll
                    for (int r = 0; r < 4; r++) S[mt][nt][r] = 0.f;

            const uint32_t base = (ng ? qk1 : qk0) + so;
            #pragma unroll
            for (int ks = 0; ks < 4; ks++) {
                uint32_t h0, h1, h2, h3;
                ldm_x4(h0, h1, h2, h3, base + ks * 32);
                mma16816(S[0][0], qf[0][ks], h0, h1);
                mma16816(S[0][1], qf[0][ks], h2, h3);
                mma16816(S[1][0], qf[1][ks], h0, h1);
                mma16816(S[1][1], qf[1][ks], h2, h3);
            }

            #pragma unroll
            for (int mt = 0; mt < 2; mt++) {
                #pragma unroll
                for (int nt = 0; nt < 2; nt++) {
                    #pragma unroll
                    for (int r = 0; r < 4; r++) S[mt][nt][r] = ex2a(S[mt][nt][r]);
                    lsum[mt][0] += S[mt][nt][0] + S[mt][nt][1];
                    lsum[mt][1] += S[mt][nt][2] + S[mt][nt][3];
                }
                pf[mt][ng][0] = packh2(S[mt][0][0], S[mt][0][1]);
                pf[mt][ng][1] = packh2(S[mt][0][2], S[mt][0][3]);
                pf[mt][ng][2] = packh2(S[mt][1][0], S[mt][1][1]);
                pf[mt][ng][3] = packh2(S[mt][1][2], S[mt][1][3]);
            }
        }

        #pragma unroll
        for (int ks = 0; ks < 2; ks++) {
            const uint32_t base = (ks ? pv1 : pv0) + so;
            #pragma unroll
            for (int dg = 0; dg < 4; dg++) {
                uint32_t v0, v1, v2, v3;
                ldm_x4t(v0, v1, v2, v3, base + dg * 32);
                mma16816(Oa[0][2 * dg],     pf[0][ks], v0, v1);
                mma16816(Oa[0][2 * dg + 1], pf[0][ks], v2, v3);
                mma16816(Oa[1][2 * dg],     pf[1][ks], v0, v1);
                mma16816(Oa[1][2 * dg + 1], pf[1][ks], v2, v3);
            }
        }
    };

    issue_kv(0); issue_kv(1); issue_kv(2);

    for (int kt4 = 0; kt4 < 7; kt4++) {
        #pragma unroll
        for (int u = 0; u < 4; u++) {
            asm volatile("cp.async.wait_group 2;");
            __syncthreads();
            issue_kv(kt4 * 4 + u + 3);
            compute(u);
        }
    }
    asm volatile("cp.async.wait_group 2;"); __syncthreads(); issue_kv(31); compute(0);
    asm volatile("cp.async.wait_group 2;"); __syncthreads(); compute(1);
    asm volatile("cp.async.wait_group 1;"); __syncthreads(); compute(2);
    asm volatile("cp.async.wait_group 0;"); __syncthreads(); compute(3);

    #pragma unroll
    for (int mt = 0; mt < 2; mt++)
        #pragma unroll
        for (int s = 0; s < 2; s++) {
            lsum[mt][s] += __shfl_xor_sync(0xffffffffu, lsum[mt][s], 1);
            lsum[mt][s] += __shfl_xor_sync(0xffffffffu, lsum[mt][s], 2);
        }

    const int b = bh / H_, h = bh % H_;
    #pragma unroll
    for (int mt = 0; mt < 2; mt++) {
        const float inv0 = 1.f / lsum[mt][0];
        const float inv1 = 1.f / lsum[mt][1];
        const size_t row0 = (size_t)b * N_ + qbase + warp * 32 + mt * 16 + (lane >> 2);
        #pragma unroll
        for (int dt = 0; dt < 8; dt++) {
            const int col = h * HD_ + dt * 8 + (lane & 3) * 2;
            *reinterpret_cast<uint32_t*>(ao + row0 * D_ + col) =
                packh2(Oa[mt][dt][0] * inv0, Oa[mt][dt][1] * inv0);
            *reinterpret_cast<uint32_t*>(ao + (row0 + 8) * D_ + col) =
                packh2(Oa[mt][dt][2] * inv1, Oa[mt][dt][3] * inv1);
        }
    }
}

// ---------------------------------------------------------------------------
extern "C" void kernel_launch(void* const* d_in, const int* in_sizes, int n_in,
                              void* d_out, int out_size)
{
    const float* x  = (const float*)d_in[0];
    const float* Wq = (const float*)d_in[1];
    const float* bq = (const float*)d_in[2];
    const float* Wk = (const float*)d_in[3];
    const float* bk = (const float*)d_in[4];
    const float* Wv = (const float*)d_in[5];
    const float* bv = (const float*)d_in[6];
    const float* Wo = (const float*)d_in[7];
    const float* bo = (const float*)d_in[8];
    float* out = (float*)d_out;

    __half *xh, *w, *q, *k, *v, *ao;
    cudaGetSymbolAddress((void**)&xh, g_x);
    cudaGetSymbolAddress((void**)&w,  g_w);
    cudaGetSymbolAddress((void**)&q,  g_q);
    cudaGetSymbolAddress((void**)&k,  g_k);
    cudaGetSymbolAddress((void**)&v,  g_v);
    cudaGetSymbolAddress((void**)&ao, g_ao);

    const int nx4 = M_TOT * D_ / 4;
    const int nw4 = D_ * D_ / 4;
    const size_t WS = (size_t)D_ * D_;
    const int ntot = nx4 + 4 * nw4;

    static bool attr_done = false;
    if (!attr_done) {
        cudaFuncSetAttribute(qkv_gemm, cudaFuncAttributeMaxDynamicSharedMemorySize, QSMEM);
        cudaFuncSetAttribute(out_gemm, cudaFuncAttributeMaxDynamicSharedMemorySize, OSMEM);
        attr_done = true;
    }

    convall_kernel<<<(ntot + 1023) / 1024, 256>>>(x, Wq, Wk, Wv, Wo, xh, w, nx4, nw4);

    dim3 qkvgrid(18, M_TOT / 128);
    qkv_gemm<<<qkvgrid, 256, QSMEM>>>(xh, w, bq, bk, bv, q, k, v);

    dim3 agrid(N_ / 128, B_ * H_);
    attn_mma<<<agrid, 128>>>(q, k, v, ao);

    dim3 ogrid(12, M_TOT / 128);
    out_gemm<<<ogrid, 256, OSMEM>>>(ao, w + 3 * WS, bo, out);
}